// round 15
// baseline (speedup 1.0000x reference)
#include <cuda_runtime.h>
#include <math.h>
#include <stdint.h>

// Problem constants
#define SEQ   512
#define BATCH 64
#define HID   1024
#define NIN   512
#define NOUT  512
#define BH    (BATCH * HID)
// Recurrence grid: 8 jt (128 cols) x 4 kc (256 k) x 4 bh (16 rows) = 128 CTAs
#define NKC   4

// Scratch (device globals). Layout of xi/h: [s][b][h]
__device__ float g_xi[(size_t)SEQ * BATCH * HID];
__device__ float g_h [(size_t)SEQ * BATCH * HID];
// Partials, parity double-buffered: [par][q 4][64 rows][1024 cols]
__device__ float g_part[2][NKC][BATCH][HID];

// Dataflow counters, one per (jt,bh), padded 128B apart.
// grp[jt][bh]  : phase-A completions (fan-in 4: the kc CTAs of this group)
// done[jt][bh] : phase-B completions (fan-in 4) -> h rows[16bh) cols[128jt) ready
__device__ unsigned g_grp [32 * 32];
__device__ unsigned g_done[32 * 32];

__global__ void reset_barriers()
{
    if (threadIdx.x < 32) {
        g_grp [threadIdx.x << 5] = 0;
        g_done[threadIdx.x << 5] = 0;
    }
}

__device__ __forceinline__ unsigned ld_acq(const unsigned* p)
{
    unsigned v;
    asm volatile("ld.acquire.gpu.global.u32 %0, [%1];" : "=r"(v) : "l"(p));
    return v;
}
__device__ __forceinline__ void arrive(unsigned* p)
{
    asm volatile("red.release.gpu.global.add.u32 [%0], 1;" :: "l"(p) : "memory");
}

// ---------------------------------------------------------------------------
// 128x128x8 fp32 SGEMM with bias + output-row permutation (proven, ~roofline)
// PERM=1: A row m=(b*512+s) -> C row (s*64+b)   [GEMM1: x->xi]
// PERM=2: A row m=(s*64+b)  -> C row (b*512+s)  [GEMM3: h->y]
// ---------------------------------------------------------------------------
template<int K, int N, int PERM>
__global__ __launch_bounds__(256, 2) void gemm128(
    const float* __restrict__ A, const float* __restrict__ Bm,
    const float* __restrict__ bias, float* __restrict__ C)
{
    __shared__ float As[8][132];
    __shared__ float Bs[8][128];

    const int tid = threadIdx.x;
    const int tx = tid & 15, ty = tid >> 4;
    const int row0 = blockIdx.y * 128, col0 = blockIdx.x * 128;

    const int a_r = tid >> 1, a_k = (tid & 1) << 2;
    const int b_k = tid >> 5, b_c = (tid & 31) << 2;

    const float* Ap = A + (size_t)(row0 + a_r) * K + a_k;
    const float* Bp = Bm + (size_t)b_k * N + col0 + b_c;

    float4 ar = *(const float4*)Ap;
    float4 br = *(const float4*)Bp;

    float acc[8][8] = {};

    for (int k0 = 0; k0 < K; k0 += 8) {
        As[a_k + 0][a_r] = ar.x;
        As[a_k + 1][a_r] = ar.y;
        As[a_k + 2][a_r] = ar.z;
        As[a_k + 3][a_r] = ar.w;
        *(float4*)&Bs[b_k][b_c] = br;
        __syncthreads();
        if (k0 + 8 < K) {
            ar = *(const float4*)(Ap + k0 + 8);
            br = *(const float4*)(Bp + (size_t)(k0 + 8) * N);
        }
#pragma unroll
        for (int kk = 0; kk < 8; kk++) {
            float4 a0 = *(const float4*)&As[kk][ty << 2];
            float4 a1 = *(const float4*)&As[kk][(ty << 2) + 64];
            float4 b0 = *(const float4*)&Bs[kk][tx << 2];
            float4 b1 = *(const float4*)&Bs[kk][(tx << 2) + 64];
            float av[8] = {a0.x, a0.y, a0.z, a0.w, a1.x, a1.y, a1.z, a1.w};
            float bv[8] = {b0.x, b0.y, b0.z, b0.w, b1.x, b1.y, b1.z, b1.w};
#pragma unroll
            for (int i = 0; i < 8; i++)
#pragma unroll
                for (int j = 0; j < 8; j++)
                    acc[i][j] = fmaf(av[i], bv[j], acc[i][j]);
        }
        __syncthreads();
    }

    float4 bb0 = *(const float4*)&bias[col0 + (tx << 2)];
    float4 bb1 = *(const float4*)&bias[col0 + (tx << 2) + 64];
#pragma unroll
    for (int i = 0; i < 8; i++) {
        const int mloc = (i < 4) ? ((ty << 2) + i) : ((ty << 2) + i + 60);
        const int m = row0 + mloc;
        size_t r;
        if (PERM == 1)      r = (size_t)((m & 511) * 64 + (m >> 9));
        else if (PERM == 2) r = (size_t)((m & 63) * 512 + (m >> 6));
        else                r = (size_t)m;
        float* Cr = C + r * N + col0;
        float4 o0 = make_float4(acc[i][0] + bb0.x, acc[i][1] + bb0.y,
                                acc[i][2] + bb0.z, acc[i][3] + bb0.w);
        float4 o1 = make_float4(acc[i][4] + bb1.x, acc[i][5] + bb1.y,
                                acc[i][6] + bb1.z, acc[i][7] + bb1.w);
        *(float4*)(Cr + (tx << 2)) = o0;
        *(float4*)(Cr + (tx << 2) + 64) = o1;
    }
}

// ---------------------------------------------------------------------------
// Persistent recurrence, fan-in 4 + split A-wait.
// CTA = (jt = bx&7 -> cols[128jt), kc = (bx>>3)&3 -> k[256kc), bh = bx>>5 ->
// rows[16bh)). Wh slice [256k][128j] smem-resident (128KB).
// Phase A: for half 0,1: wait done[2kc+half][bh]>=4t -> GEMM over 128 k.
//   (second wait hides behind first half's compute)
// Phase B: prefetch xi -> wait grp[jt][bh]>=4t -> reduce 4 rows from 4
//   partials, tanh, relu -> g_h -> arrive done[jt][bh].
// ---------------------------------------------------------------------------
#define RNN_DSMEM ((256 * 128 + 16 * 36) * 4)   // 133376 B

__global__ __launch_bounds__(128) void rnn_recurrence(const float* __restrict__ Wh)
{
    extern __shared__ float dsm[];
    float* Bs = dsm;                   // [256 k][128 j]
    float* As = dsm + 256 * 128;       // [16 k][36 rows] (144B rows, 16B-aligned)

    const int tid = threadIdx.x;
    const int jt  = blockIdx.x & 7;
    const int kc  = (blockIdx.x >> 3) & 3;
    const int bhh = blockIdx.x >> 5;
    const int col0  = jt << 7;
    const int kbase = kc << 8;
    const int rbase = bhh << 4;
    const int w  = tid >> 5;                  // warp 0..3 -> 4 rows each
    const int tx = tid & 31;                  // 4 cols each
    const int a_r = tid >> 3;                 // staging row 0..15
    const int a_k = (tid & 7) << 1;           // staging k pair
    const int own = ((jt << 2) | bhh) << 5;

    // Load persistent Wh slice [256k][128j] (one-time, 128KB)
    for (int i = 0; i < 64; i++) {
        const int e4 = i * 128 + tid;              // float4 index
        const int k = e4 >> 5, c = (e4 & 31) << 2;
        *(float4*)&Bs[k * 128 + c] =
            *(const float4*)&Wh[(size_t)(kbase + k) * HID + col0 + c];
    }

    // h_0 init on this CTA's phase-B slice: rows rbase+4kc+w, 128 cols
    {
        const int row = rbase + (kc << 2) + w;
        const int cc = col0 + (tx << 2);
        const size_t off = (size_t)row * HID + cc;
        float4 v = *(const float4*)&g_xi[off];
        v.x = fmaxf(tanhf(v.x), 0.0f);
        v.y = fmaxf(tanhf(v.y), 0.0f);
        v.z = fmaxf(tanhf(v.z), 0.0f);
        v.w = fmaxf(tanhf(v.w), 0.0f);
        *(float4*)&g_h[off] = v;
    }
    __syncthreads();
    if (tid == 0) arrive(&g_done[own]);

    for (int t = 1; t < SEQ; t++) {
        const unsigned target = 4u * (unsigned)t;
        const float* hprev = g_h + (size_t)(t - 1) * BH;
        float acc[4][4] = {};

        // ---- phase A over two 128-k halves, each gated on its producer ----
#pragma unroll
        for (int half = 0; half < 2; half++) {
            const int srcidx = ((((kc << 1) | half) << 2) | bhh) << 5;
            while (ld_acq(&g_done[srcidx]) < target) {}

            const int kh = (half << 7);            // k offset within chunk
            const float* hrow = hprev + (size_t)(rbase + a_r) * HID
                                + kbase + kh + a_k;
            float2 pa = *(const float2*)hrow;

            for (int k0 = 0; k0 < 128; k0 += 16) {
                As[(a_k + 0) * 36 + a_r] = pa.x;
                As[(a_k + 1) * 36 + a_r] = pa.y;
                __syncthreads();
                if (k0 + 16 < 128)
                    pa = *(const float2*)(hrow + k0 + 16);
#pragma unroll
                for (int kk = 0; kk < 16; kk++) {
                    float4 a = *(const float4*)&As[kk * 36 + (w << 2)];
                    float4 b = *(const float4*)&Bs[(kh + k0 + kk) * 128 + (tx << 2)];
                    float av[4] = {a.x, a.y, a.z, a.w};
                    float bv[4] = {b.x, b.y, b.z, b.w};
#pragma unroll
                    for (int i = 0; i < 4; i++)
#pragma unroll
                        for (int j = 0; j < 4; j++)
                            acc[i][j] = fmaf(av[i], bv[j], acc[i][j]);
                }
                __syncthreads();
            }
        }

        // store partials: rows rbase + w*4 + i, cols col0 + tx*4
        {
            float* pd = &g_part[t & 1][kc][0][0];
#pragma unroll
            for (int i = 0; i < 4; i++) {
                const int row = rbase + (w << 2) + i;
                *(float4*)&pd[(size_t)row * HID + col0 + (tx << 2)] =
                    make_float4(acc[i][0], acc[i][1], acc[i][2], acc[i][3]);
            }
        }
        __syncthreads();
        if (tid == 0) arrive(&g_grp[own]);

        // ---- phase B: reduce own 4-row slice from 4 partials ----
        {
            const int row = rbase + (kc << 2) + w;
            const int cc = col0 + (tx << 2);
            const size_t eo = (size_t)row * HID + cc;
            const size_t off = (size_t)t * BH + eo;
            float4 v = *(const float4*)&g_xi[off];   // prefetch before wait

            while (ld_acq(&g_grp[own]) < target) {}

            const float* pt = &g_part[t & 1][0][0][0];
#pragma unroll
            for (int q = 0; q < NKC; q++) {
                float4 p = *(const float4*)&pt[(size_t)q * BH + eo];
                v.x += p.x; v.y += p.y; v.z += p.z; v.w += p.w;
            }
            v.x = fmaxf(tanhf(v.x), 0.0f);
            v.y = fmaxf(tanhf(v.y), 0.0f);
            v.z = fmaxf(tanhf(v.z), 0.0f);
            v.w = fmaxf(tanhf(v.w), 0.0f);
            *(float4*)&g_h[off] = v;
        }
        __syncthreads();
        if (tid == 0) arrive(&g_done[own]);
    }
}

// ---------------------------------------------------------------------------
extern "C" void kernel_launch(void* const* d_in, const int* in_sizes, int n_in,
                              void* d_out, int out_size)
{
    const float* x  = (const float*)d_in[0];
    const float* Wi = (const float*)d_in[1];
    const float* bi = (const float*)d_in[2];
    const float* Wh = (const float*)d_in[3];
    const float* Wo = (const float*)d_in[4];
    const float* bo = (const float*)d_in[5];
    float* out = (float*)d_out;

    void* p;
    cudaGetSymbolAddress(&p, g_xi);
    float* xi = (float*)p;
    cudaGetSymbolAddress(&p, g_h);
    float* hh = (float*)p;

    cudaFuncSetAttribute(rnn_recurrence,
                         cudaFuncAttributeMaxDynamicSharedMemorySize, RNN_DSMEM);

    // 0) zero dataflow counters so every graph replay starts clean
    reset_barriers<<<1, 32>>>();

    // 1) xi[s][b][h] = x @ Wi + bi   (fp32, ~roofline)
    gemm128<NIN, HID, 1><<<dim3(HID / 128, (BATCH * SEQ) / 128), 256>>>(x, Wi, bi, xi);

    // 2) recurrence: fan-in-4 persistent kernel, split A-wait
    rnn_recurrence<<<128, 128, RNN_DSMEM>>>(Wh);

    // 3) y[b][s][o] = h @ Wo + bo    (fp32, ~roofline)
    gemm128<HID, NOUT, 2><<<dim3(NOUT / 128, (BATCH * SEQ) / 128), 256>>>(hh, Wo, bo, out);
}